// round 13
// baseline (speedup 1.0000x reference)
#include <cuda_runtime.h>
#include <cstdint>
#include <cstddef>

#define B_ 4
#define S_ 2048
#define D_ 768
#define NH_ 4
#define DH_ 192
#define KC_ 4

// cluster split of the recurrence
#define CL 8            // CTAs per (b,h) cluster
#define EPB 24          // DH / CL output columns per CTA
#define TPB 192         // 2 threads per output (96 outputs), d-dim halves
#define QSTR 56         // padded quarter stride (floats): 48 data + 8 pad
#define BUFSTR (4 * QSTR)  // 224 floats per h buffer
#define TXB (CL * EPB * 4) // 768 bytes expected per barrier phase
#define GATE0 160       // first gating thread (warp 5)
#define SEND0 184       // first sender thread (warp 5)

// scratch (device globals: allocation-free)
__device__ float d_xconv[B_ * S_ * D_];                 // 25.2 MB
__device__ float d_G[S_ * B_ * NH_ * 4 * DH_];          // 100.7 MB, layout [S][B][NH*4][DH]

// ---------------------------------------------------------------------------
// 1) causal depthwise conv1d + swish
// ---------------------------------------------------------------------------
__global__ __launch_bounds__(256) void conv_swish_kernel(
    const float* __restrict__ x, const float* __restrict__ ck,
    const float* __restrict__ cb, float* __restrict__ xc)
{
    int idx = blockIdx.x * 256 + threadIdx.x;       // < B*S*D
    int d = idx % D_;
    int s = (idx / D_) & (S_ - 1);
    float acc = cb[d];
#pragma unroll
    for (int k = 0; k < KC_; k++) {
        int ss = s - (KC_ - 1) + k;
        if (ss >= 0) acc = fmaf(x[idx + (k - (KC_ - 1)) * D_], ck[k * D_ + d], acc);
    }
    xc[idx] = acc / (1.f + expf(-acc));             // swish
}

// ---------------------------------------------------------------------------
// 2) gate pre-activation GEMMs: G[s][b][h][g][e] = xin . W[g,h] + cell_bias
//    128x96 tile, 192 threads, 8x8 outputs/thread, packed fma.rn.f32x2
// ---------------------------------------------------------------------------
__global__ __launch_bounds__(192) void gate_gemm_kernel(
    const float* __restrict__ x, const float* __restrict__ xc,
    const float* __restrict__ Wi, const float* __restrict__ Wf,
    const float* __restrict__ Wz, const float* __restrict__ Wo,
    const float* __restrict__ cb, float* __restrict__ G)
{
    __shared__ __align__(16) float As[16 * 132];   // [k][m], padded
    __shared__ __align__(16) float Bs[16 * 100];   // [k][n], padded

    const int z = blockIdx.z;                      // h*4+g
    const int h = z >> 2;
    const int g = z & 3;
    const float* A = (g < 2 ? xc : x) + h * DH_;   // row stride D_
    const float* W = (g == 0 ? Wi : g == 1 ? Wf : g == 2 ? Wz : Wo) + h * DH_ * DH_;
    const int m0 = blockIdx.x * 128;
    const int n0 = blockIdx.y * 96;
    const int tid = threadIdx.x;
    const int ty = tid / 12;                       // 0..15 -> rows ty*8..+8
    const int tx = tid % 12;                       // 0..11 -> cols tx*8..+8

    uint64_t acc2[4][8];                           // 4 row-pairs x 8 cols
#pragma unroll
    for (int i = 0; i < 4; i++)
#pragma unroll
        for (int j = 0; j < 8; j++) acc2[i][j] = 0ull;

    for (int k0 = 0; k0 < DH_; k0 += 16) {
        // A tile 128x16 -> As transposed ([k][m]); 512 float4
        for (int i = tid; i < 512; i += 192) {
            int r = i >> 2, cc = i & 3;
            float4 v = *(const float4*)(A + (size_t)(m0 + r) * D_ + k0 + cc * 4);
            As[(cc * 4 + 0) * 132 + r] = v.x;
            As[(cc * 4 + 1) * 132 + r] = v.y;
            As[(cc * 4 + 2) * 132 + r] = v.z;
            As[(cc * 4 + 3) * 132 + r] = v.w;
        }
        // B tile 16x96; 384 float4
        for (int i = tid; i < 384; i += 192) {
            int r = i / 24, cc = i % 24;
            float4 v = *(const float4*)(W + (size_t)(k0 + r) * DH_ + n0 + cc * 4);
            *(float4*)(Bs + r * 100 + cc * 4) = v;
        }
        __syncthreads();
#pragma unroll
        for (int k = 0; k < 16; k++) {
            const ulonglong2* ar = (const ulonglong2*)(As + k * 132 + ty * 8);
            ulonglong2 aP0 = ar[0];
            ulonglong2 aP1 = ar[1];
            float4 b0 = *(const float4*)(Bs + k * 100 + tx * 8);
            float4 b1 = *(const float4*)(Bs + k * 100 + tx * 8 + 4);
            uint64_t bp[8];
            asm("mov.b64 %0, {%1, %1};" : "=l"(bp[0]) : "f"(b0.x));
            asm("mov.b64 %0, {%1, %1};" : "=l"(bp[1]) : "f"(b0.y));
            asm("mov.b64 %0, {%1, %1};" : "=l"(bp[2]) : "f"(b0.z));
            asm("mov.b64 %0, {%1, %1};" : "=l"(bp[3]) : "f"(b0.w));
            asm("mov.b64 %0, {%1, %1};" : "=l"(bp[4]) : "f"(b1.x));
            asm("mov.b64 %0, {%1, %1};" : "=l"(bp[5]) : "f"(b1.y));
            asm("mov.b64 %0, {%1, %1};" : "=l"(bp[6]) : "f"(b1.z));
            asm("mov.b64 %0, {%1, %1};" : "=l"(bp[7]) : "f"(b1.w));
#pragma unroll
            for (int j = 0; j < 8; j++) {
                asm("fma.rn.f32x2 %0, %1, %2, %0;" : "+l"(acc2[0][j]) : "l"(aP0.x), "l"(bp[j]));
                asm("fma.rn.f32x2 %0, %1, %2, %0;" : "+l"(acc2[1][j]) : "l"(aP0.y), "l"(bp[j]));
                asm("fma.rn.f32x2 %0, %1, %2, %0;" : "+l"(acc2[2][j]) : "l"(aP1.x), "l"(bp[j]));
                asm("fma.rn.f32x2 %0, %1, %2, %0;" : "+l"(acc2[3][j]) : "l"(aP1.y), "l"(bp[j]));
            }
        }
        __syncthreads();
    }

    // epilogue: scatter into [S][B][NH*4][DH] layout + cell_bias
#pragma unroll
    for (int i = 0; i < 8; i++) {
        int m = m0 + ty * 8 + i;
        int bb_ = m >> 11;            // m = b*S + s
        int s_ = m & (S_ - 1);
        float* op = G + ((size_t)(s_ * B_ + bb_) * 16 + z) * DH_ + n0 + tx * 8;
        const float* cbp = cb + (size_t)g * D_ + h * DH_ + n0 + tx * 8;
#pragma unroll
        for (int j = 0; j < 8; j++) {
            float lo, hi;
            asm("mov.b64 {%0, %1}, %2;" : "=f"(lo), "=f"(hi) : "l"(acc2[i >> 1][j]));
            op[j] = ((i & 1) ? hi : lo) + cbp[j];
        }
    }
}

// ---------------------------------------------------------------------------
// 3) sequential scan: 16 clusters of 8 CTAs; each cluster owns one (b,h).
//    6 warps per CTA; R register-resident (f32x2 packed, 96 floats/thread).
//    Critical-path threads (gating + senders) live in the TOP warp (hi-wid
//    arbiter priority). h exchanged via cp.async.bulk (one 96B copy per
//    destination) completing tx-counting mbarriers.  [identical to R10]
// ---------------------------------------------------------------------------
__device__ __forceinline__ void mbar_wait_cta(uint32_t mbar, uint32_t parity) {
    asm volatile(
        "{\n\t"
        ".reg .pred P1;\n\t"
        "WL_%=:\n\t"
        "mbarrier.try_wait.parity.acquire.cta.shared::cta.b64 P1, [%0], %1, 0x989680;\n\t"
        "@P1 bra.uni WD_%=;\n\t"
        "bra.uni WL_%=;\n\t"
        "WD_%=:\n\t"
        "}"
        :: "r"(mbar), "r"(parity) : "memory");
}

__global__ void __cluster_dims__(CL, 1, 1) __launch_bounds__(TPB, 1)
scan_kernel(const float* __restrict__ G, const float* __restrict__ Rw,
            float* __restrict__ out)
{
    __shared__ __align__(16) float hs[2 * BUFSTR];    // double-buffered h (padded)
    __shared__ __align__(16) float stage[2][EPB];     // outgoing h chunks (double-buffered)
    __shared__ float pres[96];                        // 4 gates * EPB
    __shared__ __align__(8) unsigned long long fm[2]; // tx full barriers per buffer

    const int tid  = threadIdx.x;
    const int grp  = blockIdx.x >> 3;      // (b,h) group 0..15
    const int rank = blockIdx.x & (CL - 1);
    const int b = grp >> 2;
    const int h = grp & 3;

    const int o    = tid >> 1;             // output 0..95  (g*EPB + e)
    const int half = tid & 1;              // d-range half: [96*half, 96*half+96)
    const int dg   = o / EPB;
    const int de   = o % EPB;
    const int col  = rank * EPB + de;

    // ---- R slice packed into f32x2 regs: 96 floats = 48 pairs
    uint64_t Rp[48];
    {
        const float* Rb = Rw + ((size_t)(dg * NH_ + h) * DH_ + half * 96) * DH_ + col;
#pragma unroll
        for (int i = 0; i < 24; i++) {
            float r0 = Rb[(size_t)(4 * i + 0) * DH_];
            float r1 = Rb[(size_t)(4 * i + 1) * DH_];
            float r2 = Rb[(size_t)(4 * i + 2) * DH_];
            float r3 = Rb[(size_t)(4 * i + 3) * DH_];
            asm("mov.b64 %0, {%1, %2};" : "=l"(Rp[2 * i])     : "f"(r0), "f"(r1));
            asm("mov.b64 %0, {%1, %2};" : "=l"(Rp[2 * i + 1]) : "f"(r2), "f"(r3));
        }
    }

    for (int i = tid; i < 2 * BUFSTR; i += TPB) hs[i] = 0.f;
    const uint32_t fm_local = (uint32_t)__cvta_generic_to_shared(&fm[0]);
    if (tid == 0) {
        asm volatile("mbarrier.init.shared.b64 [%0], %1;" :: "r"(fm_local),     "r"(1) : "memory");
        asm volatile("mbarrier.init.shared.b64 [%0], %1;" :: "r"(fm_local + 8), "r"(1) : "memory");
        // arm phase 0 of both barriers (t=0 sends -> fm[1], t=1 sends -> fm[0])
        asm volatile("mbarrier.arrive.expect_tx.shared.b64 _, [%0], %1;" :: "r"(fm_local),     "r"(TXB) : "memory");
        asm volatile("mbarrier.arrive.expect_tx.shared.b64 _, [%0], %1;" :: "r"(fm_local + 8), "r"(TXB) : "memory");
    }
    __syncthreads();
    asm volatile("barrier.cluster.arrive.aligned;" ::: "memory");
    asm volatile("barrier.cluster.wait.aligned;"   ::: "memory");

    // sender thread (SEND0+r) ships this CTA's 96B chunk to rank r:
    // dst slot (buffer 0) = hs + (rank/2)*QSTR + (rank&1)*EPB in CTA r
    uint32_t hrem = 0, frem = 0;
    if (tid >= SEND0) {
        int dr = tid - SEND0;              // destination rank
        uint32_t la = (uint32_t)__cvta_generic_to_shared(
            &hs[(rank >> 1) * QSTR + (rank & 1) * EPB]);
        asm volatile("mapa.shared::cluster.u32 %0, %1, %2;" : "=r"(hrem) : "r"(la), "r"(dr));
        asm volatile("mapa.shared::cluster.u32 %0, %1, %2;" : "=r"(frem) : "r"(fm_local), "r"(dr));
    }
    const uint32_t stage_base = (uint32_t)__cvta_generic_to_shared(&stage[0][0]);

    const float* Gp = G + (size_t)(b * 16 + h * 4 + dg) * DH_ + col;
    const int GSTRIDE = B_ * 16 * DH_;     // 12288
    float gin = (half == 0) ? Gp[0] : 0.f;

    float c = 0.f, n = 0.f, mst = 0.f;
    const int ge = tid - GATE0;            // gating element, valid for 0<=ge<EPB
    float* outp = out + (size_t)b * S_ * D_ + h * DH_ + rank * EPB + ge;
    int ph0 = 0, ph1 = 0;

#pragma unroll 1
    for (int t = 0; t < S_; ++t) {
        const int j = t & 1;
        if (t > 0) {
            if (j) { mbar_wait_cta(fm_local + 8, (uint32_t)ph1); ph1 ^= 1; }
            else   { mbar_wait_cta(fm_local,     (uint32_t)ph0); ph0 ^= 1; }
            if (tid == SEND0 + 7)   // re-arm this barrier for step t+2's data
                asm volatile("mbarrier.arrive.expect_tx.shared.b64 _, [%0], %1;"
                             :: "r"(fm_local + j * 8), "r"(TXB) : "memory");
        }

        // dot over d-range [96*half, 96*half+96): quarters 2*half and 2*half+1
        const ulonglong2* hvA = (const ulonglong2*)(hs + j * BUFSTR + (2 * half) * QSTR);
        const ulonglong2* hvB = (const ulonglong2*)(hs + j * BUFSTR + (2 * half + 1) * QSTR);
        uint64_t acc01 = 0ull, acc23 = 0ull;     // packed {0.f, 0.f}
#pragma unroll
        for (int i = 0; i < 12; i++) {
            ulonglong2 hp = hvA[i];
            asm("fma.rn.f32x2 %0, %1, %2, %0;" : "+l"(acc01) : "l"(Rp[2 * i]),     "l"(hp.x));
            asm("fma.rn.f32x2 %0, %1, %2, %0;" : "+l"(acc23) : "l"(Rp[2 * i + 1]), "l"(hp.y));
        }
#pragma unroll
        for (int i = 0; i < 12; i++) {
            ulonglong2 hp = hvB[i];
            asm("fma.rn.f32x2 %0, %1, %2, %0;" : "+l"(acc01) : "l"(Rp[24 + 2 * i]),     "l"(hp.x));
            asm("fma.rn.f32x2 %0, %1, %2, %0;" : "+l"(acc23) : "l"(Rp[24 + 2 * i + 1]), "l"(hp.y));
        }
        float a0, a1, a2, a3;
        asm("mov.b64 {%0, %1}, %2;" : "=f"(a0), "=f"(a1) : "l"(acc01));
        asm("mov.b64 {%0, %1}, %2;" : "=f"(a2), "=f"(a3) : "l"(acc23));
        float sum = (a0 + a1) + (a2 + a3);
        sum += __shfl_xor_sync(0xFFFFFFFFu, sum, 1);
        if (half == 0) {
            pres[o] = sum + gin;
            if (t + 1 < S_) gin = Gp[(size_t)(t + 1) * GSTRIDE];   // prefetch
        }
        __syncthreads();                              // S1

        if (tid >= GATE0) {
            float hnew = 0.f;
            if (tid < GATE0 + EPB) {
                float it = pres[ge];
                float ft = pres[EPB + ge];
                float zt = pres[2 * EPB + ge];
                float ot = pres[3 * EPB + ge];
                float mn = fmaxf(ft + mst, it);
                float ia = __expf(it - mn);               // arg <= 0
                float fa = __expf(ft + mst - mn);         // arg <= 0
                float e2 = __expf(2.f * zt);
                float tz = 1.f - __fdividef(2.f, e2 + 1.f);   // tanh, NaN-safe at +-inf
                c = fa * c + ia * tz;
                n = fa * n + ia;
                mst = mn;
                float sig = __fdividef(1.f, 1.f + __expf(-ot));
                hnew = sig * __fdividef(c, n);
                stage[j][ge] = hnew;
            }
            __syncwarp();                             // warp 5: stage visible to senders
            if (t + 1 < S_ && tid >= SEND0) {
                asm volatile("fence.proxy.async.shared::cta;" ::: "memory");
                uint32_t dst = hrem + (uint32_t)((j ^ 1) * (BUFSTR * 4));
                uint32_t mb  = frem + (uint32_t)((j ^ 1) * 8);
                uint32_t src = stage_base + (uint32_t)(j * (EPB * 4));
                asm volatile(
                    "cp.async.bulk.shared::cluster.shared::cta.mbarrier::complete_tx::bytes "
                    "[%0], [%1], %2, [%3];"
                    :: "r"(dst), "r"(src), "r"((uint32_t)(EPB * 4)), "r"(mb) : "memory");
            }
            if (tid < GATE0 + EPB)
                outp[(size_t)t * D_] = hnew;          // global store after sends
        }
    }

    asm volatile("barrier.cluster.arrive.aligned;" ::: "memory");
    asm volatile("barrier.cluster.wait.aligned;"   ::: "memory");
}

// ---------------------------------------------------------------------------
// 4) in-place multi-head LayerNorm over DH per (b,s,h); warp per row
// ---------------------------------------------------------------------------
__global__ __launch_bounds__(256) void gnorm_kernel(
    float* __restrict__ out, const float* __restrict__ gs)
{
    int warp = (blockIdx.x * 256 + threadIdx.x) >> 5;  // row id, 32768 rows
    int lane = threadIdx.x & 31;
    float* base = out + (size_t)warp * DH_;
    int h = warp & (NH_ - 1);

    float v[6], s = 0.f, sq = 0.f;
#pragma unroll
    for (int j = 0; j < 6; j++) {
        v[j] = base[lane + 32 * j];
        s += v[j];
        sq += v[j] * v[j];
    }
#pragma unroll
    for (int o = 16; o > 0; o >>= 1) {
        s += __shfl_xor_sync(0xFFFFFFFFu, s, o);
        sq += __shfl_xor_sync(0xFFFFFFFFu, sq, o);
    }
    float mean = s * (1.f / DH_);
    float var = sq * (1.f / DH_) - mean * mean;
    float inv = rsqrtf(var + 1e-5f);
#pragma unroll
    for (int j = 0; j < 6; j++)
        base[lane + 32 * j] = (v[j] - mean) * inv * gs[h * DH_ + lane + 32 * j];
}

// ---------------------------------------------------------------------------
// launcher
// ---------------------------------------------------------------------------
extern "C" void kernel_launch(void* const* d_in, const int* in_sizes, int n_in,
                              void* d_out, int out_size)
{
    const float* x   = (const float*)d_in[0];
    const float* ck  = (const float*)d_in[1];
    const float* cb  = (const float*)d_in[2];
    const float* Wi  = (const float*)d_in[3];
    const float* Wf  = (const float*)d_in[4];
    const float* Wz  = (const float*)d_in[5];
    const float* Wo  = (const float*)d_in[6];
    const float* Rw  = (const float*)d_in[7];
    const float* cbias = (const float*)d_in[8];
    const float* gsc = (const float*)d_in[9];
    float* out = (float*)d_out;

    float* xconv; float* G;
    cudaGetSymbolAddress((void**)&xconv, d_xconv);
    cudaGetSymbolAddress((void**)&G, d_G);

    // 1) conv + swish
    conv_swish_kernel<<<(B_ * S_ * D_) / 256, 256>>>(x, ck, cb, xconv);

    // 2) gate GEMMs (128x96 tiles, 192 threads, dense f32x2 inner loop)
    dim3 ggrid((B_ * S_) / 128, DH_ * 2 / 96 / 2 * 2 / 2 + 1, NH_ * 4); // computed below
    ggrid = dim3((B_ * S_) / 128, 2, NH_ * 4);                           // 64 x 2 x 16
    gate_gemm_kernel<<<ggrid, 192>>>(x, xconv, Wi, Wf, Wz, Wo, cbias, G);

    // 3) scan (clustered: 6 warps, top-warp critical path, bulk exchange)
    scan_kernel<<<B_ * NH_ * CL, TPB>>>(G, Rw, out);

    // 4) per-head layernorm in-place
    gnorm_kernel<<<(B_ * S_ * NH_) / 8, 256>>>(out, gsc);
}

// round 14
// speedup vs baseline: 1.1038x; 1.1038x over previous
#include <cuda_runtime.h>
#include <cstdint>
#include <cstddef>

#define B_ 4
#define S_ 2048
#define D_ 768
#define NH_ 4
#define DH_ 192
#define KC_ 4

// cluster split of the recurrence
#define CL 8            // CTAs per (b,h) cluster
#define EPB 24          // DH / CL output columns per CTA
#define TPB 192         // 2 threads per output (96 outputs), d-dim halves
#define QSTR 56         // padded quarter stride (floats): 48 data + 8 pad
#define BUFSTR (4 * QSTR)  // 224 floats per h buffer
#define TXB (CL * EPB * 4) // 768 bytes expected per barrier phase
#define GATE0 160       // first gating thread (warp 5)
#define SEND0 184       // first sender thread (warp 5)

// scratch (device globals: allocation-free)
__device__ float d_xconv[B_ * S_ * D_];                 // 25.2 MB
__device__ float d_G[S_ * B_ * NH_ * 4 * DH_];          // 100.7 MB, layout [S][B][NH*4][DH]

// ---------------------------------------------------------------------------
// 1) causal depthwise conv1d + swish
// ---------------------------------------------------------------------------
__global__ __launch_bounds__(256) void conv_swish_kernel(
    const float* __restrict__ x, const float* __restrict__ ck,
    const float* __restrict__ cb, float* __restrict__ xc)
{
    int idx = blockIdx.x * 256 + threadIdx.x;       // < B*S*D
    int d = idx % D_;
    int s = (idx / D_) & (S_ - 1);
    float acc = cb[d];
#pragma unroll
    for (int k = 0; k < KC_; k++) {
        int ss = s - (KC_ - 1) + k;
        if (ss >= 0) acc = fmaf(x[idx + (k - (KC_ - 1)) * D_], ck[k * D_ + d], acc);
    }
    xc[idx] = acc / (1.f + expf(-acc));             // swish
}

// ---------------------------------------------------------------------------
// 2) gate pre-activation GEMMs: G[s][b][h][g][e] = xin . W[g,h] + cell_bias
//    [exact R10 version: 128x64 tiles, 256 threads, f32x2 inner loop]
// ---------------------------------------------------------------------------
__global__ __launch_bounds__(256) void gate_gemm_kernel(
    const float* __restrict__ x, const float* __restrict__ xc,
    const float* __restrict__ Wi, const float* __restrict__ Wf,
    const float* __restrict__ Wz, const float* __restrict__ Wo,
    const float* __restrict__ cb, float* __restrict__ G)
{
    __shared__ __align__(16) float As[16 * 132];   // [k][m], padded
    __shared__ __align__(16) float Bs[16 * 68];    // [k][n], padded

    const int z = blockIdx.z;
    const int h = z >> 2;
    const int g = z & 3;
    const float* A = (g < 2 ? xc : x) + h * DH_;                 // row stride D_
    const float* W = (g == 0 ? Wi : g == 1 ? Wf : g == 2 ? Wz : Wo) + h * DH_ * DH_;
    const int m0 = blockIdx.x * 128;
    const int n0 = blockIdx.y * 64;
    const int tid = threadIdx.x;
    const int tx = tid & 15, ty = tid >> 4;

    // acc2[ip][j]: packed pair of outputs m = ty*8 + 2*ip, 2*ip+1 for col j
    uint64_t acc2[4][4];
#pragma unroll
    for (int i = 0; i < 4; i++)
#pragma unroll
        for (int j = 0; j < 4; j++) acc2[i][j] = 0ull;

    for (int k0 = 0; k0 < DH_; k0 += 16) {
        // A tile 128x16 -> As transposed ([k][m])
#pragma unroll
        for (int l = 0; l < 2; l++) {
            int fid = tid + l * 256;
            int r = fid >> 2, cc = fid & 3;
            float4 v = *(const float4*)(A + (size_t)(m0 + r) * D_ + k0 + cc * 4);
            As[(cc * 4 + 0) * 132 + r] = v.x;
            As[(cc * 4 + 1) * 132 + r] = v.y;
            As[(cc * 4 + 2) * 132 + r] = v.z;
            As[(cc * 4 + 3) * 132 + r] = v.w;
        }
        // B tile 16x64
        {
            int r = tid >> 4, cc = tid & 15;
            float4 v = *(const float4*)(W + (k0 + r) * DH_ + n0 + cc * 4);
            *(float4*)(Bs + r * 68 + cc * 4) = v;
        }
        __syncthreads();
#pragma unroll
        for (int k = 0; k < 16; k++) {
            const ulonglong2* ar = (const ulonglong2*)(As + k * 132 + ty * 8);
            ulonglong2 aP0 = ar[0];    // {a0,a1},{a2,a3}
            ulonglong2 aP1 = ar[1];    // {a4,a5},{a6,a7}
            float4 bv = *(const float4*)(Bs + k * 68 + tx * 4);
            uint64_t bp[4];
            asm("mov.b64 %0, {%1, %1};" : "=l"(bp[0]) : "f"(bv.x));
            asm("mov.b64 %0, {%1, %1};" : "=l"(bp[1]) : "f"(bv.y));
            asm("mov.b64 %0, {%1, %1};" : "=l"(bp[2]) : "f"(bv.z));
            asm("mov.b64 %0, {%1, %1};" : "=l"(bp[3]) : "f"(bv.w));
#pragma unroll
            for (int j = 0; j < 4; j++) {
                asm("fma.rn.f32x2 %0, %1, %2, %0;" : "+l"(acc2[0][j]) : "l"(aP0.x), "l"(bp[j]));
                asm("fma.rn.f32x2 %0, %1, %2, %0;" : "+l"(acc2[1][j]) : "l"(aP0.y), "l"(bp[j]));
                asm("fma.rn.f32x2 %0, %1, %2, %0;" : "+l"(acc2[2][j]) : "l"(aP1.x), "l"(bp[j]));
                asm("fma.rn.f32x2 %0, %1, %2, %0;" : "+l"(acc2[3][j]) : "l"(aP1.y), "l"(bp[j]));
            }
        }
        __syncthreads();
    }

    // epilogue: scatter into [S][B][NH*4][DH] layout + cell_bias
#pragma unroll
    for (int i = 0; i < 8; i++) {
        int m = m0 + ty * 8 + i;
        int bb_ = m >> 11;            // m = b*S + s
        int s_ = m & (S_ - 1);
        float* op = G + ((size_t)(s_ * B_ + bb_) * 16 + z) * DH_ + n0 + tx * 4;
        const float* cbp = cb + g * D_ + h * DH_ + n0 + tx * 4;
#pragma unroll
        for (int j = 0; j < 4; j++) {
            float lo, hi;
            asm("mov.b64 {%0, %1}, %2;" : "=f"(lo), "=f"(hi) : "l"(acc2[i >> 1][j]));
            op[j] = ((i & 1) ? hi : lo) + cbp[j];
        }
    }
}

// ---------------------------------------------------------------------------
// 3) sequential scan: 16 clusters of 8 CTAs; each cluster owns one (b,h).
//    6 warps per CTA; R register-resident (f32x2 packed, 96 floats/thread).
//    Critical-path threads (gating + senders) live in the TOP warp.
//    h exchanged via cp.async.bulk completing tx-counting mbarriers.
//    New vs R10: single-MUFU stabilized gating, fused sigmoid divide,
//    split S1 barrier (dot warps arrive-only).
// ---------------------------------------------------------------------------
__device__ __forceinline__ void mbar_wait_cta(uint32_t mbar, uint32_t parity) {
    asm volatile(
        "{\n\t"
        ".reg .pred P1;\n\t"
        "WL_%=:\n\t"
        "mbarrier.try_wait.parity.acquire.cta.shared::cta.b64 P1, [%0], %1, 0x989680;\n\t"
        "@P1 bra.uni WD_%=;\n\t"
        "bra.uni WL_%=;\n\t"
        "WD_%=:\n\t"
        "}"
        :: "r"(mbar), "r"(parity) : "memory");
}

__global__ void __cluster_dims__(CL, 1, 1) __launch_bounds__(TPB, 1)
scan_kernel(const float* __restrict__ G, const float* __restrict__ Rw,
            float* __restrict__ out)
{
    __shared__ __align__(16) float hs[2 * BUFSTR];    // double-buffered h (padded)
    __shared__ __align__(16) float stage[2][EPB];     // outgoing h chunks (double-buffered)
    __shared__ float pres[96];                        // 4 gates * EPB
    __shared__ __align__(8) unsigned long long fm[2]; // tx full barriers per buffer

    const int tid  = threadIdx.x;
    const int grp  = blockIdx.x >> 3;      // (b,h) group 0..15
    const int rank = blockIdx.x & (CL - 1);
    const int b = grp >> 2;
    const int h = grp & 3;

    const int o    = tid >> 1;             // output 0..95  (g*EPB + e)
    const int half = tid & 1;              // d-range half: [96*half, 96*half+96)
    const int dg   = o / EPB;
    const int de   = o % EPB;
    const int col  = rank * EPB + de;

    // ---- R slice packed into f32x2 regs: 96 floats = 48 pairs
    uint64_t Rp[48];
    {
        const float* Rb = Rw + ((size_t)(dg * NH_ + h) * DH_ + half * 96) * DH_ + col;
#pragma unroll
        for (int i = 0; i < 24; i++) {
            float r0 = Rb[(size_t)(4 * i + 0) * DH_];
            float r1 = Rb[(size_t)(4 * i + 1) * DH_];
            float r2 = Rb[(size_t)(4 * i + 2) * DH_];
            float r3 = Rb[(size_t)(4 * i + 3) * DH_];
            asm("mov.b64 %0, {%1, %2};" : "=l"(Rp[2 * i])     : "f"(r0), "f"(r1));
            asm("mov.b64 %0, {%1, %2};" : "=l"(Rp[2 * i + 1]) : "f"(r2), "f"(r3));
        }
    }

    for (int i = tid; i < 2 * BUFSTR; i += TPB) hs[i] = 0.f;
    const uint32_t fm_local = (uint32_t)__cvta_generic_to_shared(&fm[0]);
    if (tid == 0) {
        asm volatile("mbarrier.init.shared.b64 [%0], %1;" :: "r"(fm_local),     "r"(1) : "memory");
        asm volatile("mbarrier.init.shared.b64 [%0], %1;" :: "r"(fm_local + 8), "r"(1) : "memory");
        // arm phase 0 of both barriers (t=0 sends -> fm[1], t=1 sends -> fm[0])
        asm volatile("mbarrier.arrive.expect_tx.shared.b64 _, [%0], %1;" :: "r"(fm_local),     "r"(TXB) : "memory");
        asm volatile("mbarrier.arrive.expect_tx.shared.b64 _, [%0], %1;" :: "r"(fm_local + 8), "r"(TXB) : "memory");
    }
    __syncthreads();
    asm volatile("barrier.cluster.arrive.aligned;" ::: "memory");
    asm volatile("barrier.cluster.wait.aligned;"   ::: "memory");

    // sender thread (SEND0+r) ships this CTA's 96B chunk to rank r:
    // dst slot (buffer 0) = hs + (rank/2)*QSTR + (rank&1)*EPB in CTA r
    uint32_t hrem = 0, frem = 0;
    if (tid >= SEND0) {
        int dr = tid - SEND0;              // destination rank
        uint32_t la = (uint32_t)__cvta_generic_to_shared(
            &hs[(rank >> 1) * QSTR + (rank & 1) * EPB]);
        asm volatile("mapa.shared::cluster.u32 %0, %1, %2;" : "=r"(hrem) : "r"(la), "r"(dr));
        asm volatile("mapa.shared::cluster.u32 %0, %1, %2;" : "=r"(frem) : "r"(fm_local), "r"(dr));
    }
    const uint32_t stage_base = (uint32_t)__cvta_generic_to_shared(&stage[0][0]);

    const float* Gp = G + (size_t)(b * 16 + h * 4 + dg) * DH_ + col;
    const int GSTRIDE = B_ * 16 * DH_;     // 12288
    float gin = (half == 0) ? Gp[0] : 0.f;

    float c = 0.f, n = 0.f, mst = 0.f;
    const int ge = tid - GATE0;            // gating element, valid for 0<=ge<EPB
    float* outp = out + (size_t)b * S_ * D_ + h * DH_ + rank * EPB + ge;
    int ph0 = 0, ph1 = 0;

#pragma unroll 1
    for (int t = 0; t < S_; ++t) {
        const int j = t & 1;
        if (t > 0) {
            if (j) { mbar_wait_cta(fm_local + 8, (uint32_t)ph1); ph1 ^= 1; }
            else   { mbar_wait_cta(fm_local,     (uint32_t)ph0); ph0 ^= 1; }
            if (tid == SEND0 + 7)   // re-arm this barrier for step t+2's data
                asm volatile("mbarrier.arrive.expect_tx.shared.b64 _, [%0], %1;"
                             :: "r"(fm_local + j * 8), "r"(TXB) : "memory");
        }

        // dot over d-range [96*half, 96*half+96): quarters 2*half and 2*half+1
        const ulonglong2* hvA = (const ulonglong2*)(hs + j * BUFSTR + (2 * half) * QSTR);
        const ulonglong2* hvB = (const ulonglong2*)(hs + j * BUFSTR + (2 * half + 1) * QSTR);
        uint64_t acc01 = 0ull, acc23 = 0ull;     // packed {0.f, 0.f}
#pragma unroll
        for (int i = 0; i < 12; i++) {
            ulonglong2 hp = hvA[i];
            asm("fma.rn.f32x2 %0, %1, %2, %0;" : "+l"(acc01) : "l"(Rp[2 * i]),     "l"(hp.x));
            asm("fma.rn.f32x2 %0, %1, %2, %0;" : "+l"(acc23) : "l"(Rp[2 * i + 1]), "l"(hp.y));
        }
#pragma unroll
        for (int i = 0; i < 12; i++) {
            ulonglong2 hp = hvB[i];
            asm("fma.rn.f32x2 %0, %1, %2, %0;" : "+l"(acc01) : "l"(Rp[24 + 2 * i]),     "l"(hp.x));
            asm("fma.rn.f32x2 %0, %1, %2, %0;" : "+l"(acc23) : "l"(Rp[24 + 2 * i + 1]), "l"(hp.y));
        }
        float a0, a1, a2, a3;
        asm("mov.b64 {%0, %1}, %2;" : "=f"(a0), "=f"(a1) : "l"(acc01));
        asm("mov.b64 {%0, %1}, %2;" : "=f"(a2), "=f"(a3) : "l"(acc23));
        float sum = (a0 + a1) + (a2 + a3);
        sum += __shfl_xor_sync(0xFFFFFFFFu, sum, 1);
        if (half == 0) {
            pres[o] = sum + gin;
            if (t + 1 < S_) gin = Gp[(size_t)(t + 1) * GSTRIDE];   // prefetch
        }

        if (tid < GATE0) {
            // dot warps: arrive and drop straight into next step's mbar sleep.
            // pres(t+1) WAR is safe: the next mbar wait requires our CTA's own
            // self-send, which happens-after warp 5's pres(t) reads.
            asm volatile("bar.arrive 1, 192;" ::: "memory");
        } else {
            asm volatile("bar.sync 1, 192;" ::: "memory");    // S1 (warp 5)
            float hnew = 0.f;
            if (tid < GATE0 + EPB) {
                float it = pres[ge];
                float ft = pres[EPB + ge];
                float zt = pres[2 * EPB + ge];
                float ot = pres[3 * EPB + ge];
                float fmv = ft + mst;
                float d   = it - fmv;                     // mn = max(fmv, it)
                float e   = __expf(-fabsf(d));            // single MUFU for ia/fa
                float ia  = (d >= 0.f) ? 1.f : e;         // exp(it - mn)
                float fa  = (d >= 0.f) ? e : 1.f;         // exp(fmv - mn)
                mst = fmaxf(fmv, it);
                float e2 = __expf(2.f * zt);
                float tz = 1.f - __fdividef(2.f, e2 + 1.f);   // tanh, NaN-safe
                c = fa * c + ia * tz;
                n = fa * n + ia;
                float es = __expf(-ot);
                hnew = __fdividef(c, fmaf(n, es, n));     // sigmoid(ot)*c/n, fused
                stage[j][ge] = hnew;
            }
            __syncwarp();                             // warp 5: stage visible to senders
            if (t + 1 < S_ && tid >= SEND0) {
                asm volatile("fence.proxy.async.shared::cta;" ::: "memory");
                uint32_t dst = hrem + (uint32_t)((j ^ 1) * (BUFSTR * 4));
                uint32_t mb  = frem + (uint32_t)((j ^ 1) * 8);
                uint32_t src = stage_base + (uint32_t)(j * (EPB * 4));
                asm volatile(
                    "cp.async.bulk.shared::cluster.shared::cta.mbarrier::complete_tx::bytes "
                    "[%0], [%1], %2, [%3];"
                    :: "r"(dst), "r"(src), "r"((uint32_t)(EPB * 4)), "r"(mb) : "memory");
            }
            if (tid < GATE0 + EPB)
                outp[(size_t)t * D_] = hnew;          // global store after sends
        }
    }

    asm volatile("barrier.cluster.arrive.aligned;" ::: "memory");
    asm volatile("barrier.cluster.wait.aligned;"   ::: "memory");
}

// ---------------------------------------------------------------------------
// 4) in-place multi-head LayerNorm over DH per (b,s,h); warp per row
// ---------------------------------------------------------------------------
__global__ __launch_bounds__(256) void gnorm_kernel(
    float* __restrict__ out, const float* __restrict__ gs)
{
    int warp = (blockIdx.x * 256 + threadIdx.x) >> 5;  // row id, 32768 rows
    int lane = threadIdx.x & 31;
    float* base = out + (size_t)warp * DH_;
    int h = warp & (NH_ - 1);

    float v[6], s = 0.f, sq = 0.f;
#pragma unroll
    for (int j = 0; j < 6; j++) {
        v[j] = base[lane + 32 * j];
        s += v[j];
        sq += v[j] * v[j];
    }
#pragma unroll
    for (int o = 16; o > 0; o >>= 1) {
        s += __shfl_xor_sync(0xFFFFFFFFu, s, o);
        sq += __shfl_xor_sync(0xFFFFFFFFu, sq, o);
    }
    float mean = s * (1.f / DH_);
    float var = sq * (1.f / DH_) - mean * mean;
    float inv = rsqrtf(var + 1e-5f);
#pragma unroll
    for (int j = 0; j < 6; j++)
        base[lane + 32 * j] = (v[j] - mean) * inv * gs[h * DH_ + lane + 32 * j];
}

// ---------------------------------------------------------------------------
// launcher
// ---------------------------------------------------------------------------
extern "C" void kernel_launch(void* const* d_in, const int* in_sizes, int n_in,
                              void* d_out, int out_size)
{
    const float* x   = (const float*)d_in[0];
    const float* ck  = (const float*)d_in[1];
    const float* cb  = (const float*)d_in[2];
    const float* Wi  = (const float*)d_in[3];
    const float* Wf  = (const float*)d_in[4];
    const float* Wz  = (const float*)d_in[5];
    const float* Wo  = (const float*)d_in[6];
    const float* Rw  = (const float*)d_in[7];
    const float* cbias = (const float*)d_in[8];
    const float* gsc = (const float*)d_in[9];
    float* out = (float*)d_out;

    float* xconv; float* G;
    cudaGetSymbolAddress((void**)&xconv, d_xconv);
    cudaGetSymbolAddress((void**)&G, d_G);

    // 1) conv + swish
    conv_swish_kernel<<<(B_ * S_ * D_) / 256, 256>>>(x, ck, cb, xconv);

    // 2) gate GEMMs (R10 config: 128x64 tiles, 256 threads)
    dim3 ggrid((B_ * S_) / 128, DH_ / 64, NH_ * 4);
    gate_gemm_kernel<<<ggrid, 256>>>(x, xconv, Wi, Wf, Wz, Wo, cbias, G);

    // 3) scan (clustered: 6 warps, top-warp critical path, bulk exchange)
    scan_kernel<<<B_ * NH_ * CL, TPB>>>(G, Rw, out);

    // 4) per-head layernorm in-place
    gnorm_kernel<<<(B_ * S_ * NH_) / 8, 256>>>(out, gsc);
}

// round 16
// speedup vs baseline: 1.1289x; 1.0227x over previous
#include <cuda_runtime.h>
#include <cstdint>
#include <cstddef>

#define B_ 4
#define S_ 2048
#define D_ 768
#define NH_ 4
#define DH_ 192
#define KC_ 4

// cluster split of the recurrence
#define CL 8            // CTAs per (b,h) cluster
#define EPB 24          // DH / CL output columns per CTA
#define TPB 192         // 2 threads per output (96 outputs), warp-aligned halves
#define QSTR 56         // padded quarter stride (floats): 48 data + 8 pad
#define BUFSTR (4 * QSTR)  // 224 floats per h buffer
#define TXH (4 * EPB * 4)  // 384 bytes expected per half-barrier phase
#define GATE0 160       // first gating thread (warp 5)
#define SEND0 184       // first sender thread (warp 5)

// scratch (device globals: allocation-free)
__device__ float d_xconv[B_ * S_ * D_];                 // 25.2 MB
__device__ float d_G[S_ * B_ * NH_ * 4 * DH_];          // 100.7 MB, layout [S][B][NH*4][DH]

// ---------------------------------------------------------------------------
// 1) causal depthwise conv1d + swish
// ---------------------------------------------------------------------------
__global__ __launch_bounds__(256) void conv_swish_kernel(
    const float* __restrict__ x, const float* __restrict__ ck,
    const float* __restrict__ cb, float* __restrict__ xc)
{
    int idx = blockIdx.x * 256 + threadIdx.x;       // < B*S*D
    int d = idx % D_;
    int s = (idx / D_) & (S_ - 1);
    float acc = cb[d];
#pragma unroll
    for (int k = 0; k < KC_; k++) {
        int ss = s - (KC_ - 1) + k;
        if (ss >= 0) acc = fmaf(x[idx + (k - (KC_ - 1)) * D_], ck[k * D_ + d], acc);
    }
    xc[idx] = acc / (1.f + expf(-acc));             // swish
}

// ---------------------------------------------------------------------------
// 2) gate pre-activation GEMMs: G[s][b][h][g][e] = xin . W[g,h] + cell_bias
//    [R10 config: 128x64 tiles, 256 threads, f32x2 inner loop]
// ---------------------------------------------------------------------------
__global__ __launch_bounds__(256) void gate_gemm_kernel(
    const float* __restrict__ x, const float* __restrict__ xc,
    const float* __restrict__ Wi, const float* __restrict__ Wf,
    const float* __restrict__ Wz, const float* __restrict__ Wo,
    const float* __restrict__ cb, float* __restrict__ G)
{
    __shared__ __align__(16) float As[16 * 132];   // [k][m], padded
    __shared__ __align__(16) float Bs[16 * 68];    // [k][n], padded

    const int z = blockIdx.z;
    const int h = z >> 2;
    const int g = z & 3;
    const float* A = (g < 2 ? xc : x) + h * DH_;                 // row stride D_
    const float* W = (g == 0 ? Wi : g == 1 ? Wf : g == 2 ? Wz : Wo) + h * DH_ * DH_;
    const int m0 = blockIdx.x * 128;
    const int n0 = blockIdx.y * 64;
    const int tid = threadIdx.x;
    const int tx = tid & 15, ty = tid >> 4;

    uint64_t acc2[4][4];
#pragma unroll
    for (int i = 0; i < 4; i++)
#pragma unroll
        for (int j = 0; j < 4; j++) acc2[i][j] = 0ull;

    for (int k0 = 0; k0 < DH_; k0 += 16) {
#pragma unroll
        for (int l = 0; l < 2; l++) {
            int fid = tid + l * 256;
            int r = fid >> 2, cc = fid & 3;
            float4 v = *(const float4*)(A + (size_t)(m0 + r) * D_ + k0 + cc * 4);
            As[(cc * 4 + 0) * 132 + r] = v.x;
            As[(cc * 4 + 1) * 132 + r] = v.y;
            As[(cc * 4 + 2) * 132 + r] = v.z;
            As[(cc * 4 + 3) * 132 + r] = v.w;
        }
        {
            int r = tid >> 4, cc = tid & 15;
            float4 v = *(const float4*)(W + (k0 + r) * DH_ + n0 + cc * 4);
            *(float4*)(Bs + r * 68 + cc * 4) = v;
        }
        __syncthreads();
#pragma unroll
        for (int k = 0; k < 16; k++) {
            const ulonglong2* ar = (const ulonglong2*)(As + k * 132 + ty * 8);
            ulonglong2 aP0 = ar[0];
            ulonglong2 aP1 = ar[1];
            float4 bv = *(const float4*)(Bs + k * 68 + tx * 4);
            uint64_t bp[4];
            asm("mov.b64 %0, {%1, %1};" : "=l"(bp[0]) : "f"(bv.x));
            asm("mov.b64 %0, {%1, %1};" : "=l"(bp[1]) : "f"(bv.y));
            asm("mov.b64 %0, {%1, %1};" : "=l"(bp[2]) : "f"(bv.z));
            asm("mov.b64 %0, {%1, %1};" : "=l"(bp[3]) : "f"(bv.w));
#pragma unroll
            for (int j = 0; j < 4; j++) {
                asm("fma.rn.f32x2 %0, %1, %2, %0;" : "+l"(acc2[0][j]) : "l"(aP0.x), "l"(bp[j]));
                asm("fma.rn.f32x2 %0, %1, %2, %0;" : "+l"(acc2[1][j]) : "l"(aP0.y), "l"(bp[j]));
                asm("fma.rn.f32x2 %0, %1, %2, %0;" : "+l"(acc2[2][j]) : "l"(aP1.x), "l"(bp[j]));
                asm("fma.rn.f32x2 %0, %1, %2, %0;" : "+l"(acc2[3][j]) : "l"(aP1.y), "l"(bp[j]));
            }
        }
        __syncthreads();
    }

#pragma unroll
    for (int i = 0; i < 8; i++) {
        int m = m0 + ty * 8 + i;
        int bb_ = m >> 11;            // m = b*S + s
        int s_ = m & (S_ - 1);
        float* op = G + ((size_t)(s_ * B_ + bb_) * 16 + z) * DH_ + n0 + tx * 4;
        const float* cbp = cb + g * D_ + h * DH_ + n0 + tx * 4;
#pragma unroll
        for (int j = 0; j < 4; j++) {
            float lo, hi;
            asm("mov.b64 {%0, %1}, %2;" : "=f"(lo), "=f"(hi) : "l"(acc2[i >> 1][j]));
            op[j] = ((i & 1) ? hi : lo) + cbp[j];
        }
    }
}

// ---------------------------------------------------------------------------
// 3) sequential scan: 16 clusters of 8 CTAs; each cluster owns one (b,h).
//    Warp-aligned halves: warps 0-2 own d[0:96) (chunks from ranks 0-3,
//    barrier fmA), warps 3-5 own d[96:192) (ranks 4-7, fmB). Each half
//    waits only its own barrier -> inter-half fabric jitter overlaps dots.
//    Shfl-free reduction via double-buffered pres2. Gating/senders in warp 5.
// ---------------------------------------------------------------------------
__device__ __forceinline__ void mbar_wait_cta(uint32_t mbar, uint32_t parity) {
    asm volatile(
        "{\n\t"
        ".reg .pred P1;\n\t"
        "WL_%=:\n\t"
        "mbarrier.try_wait.parity.acquire.cta.shared::cta.b64 P1, [%0], %1, 0x989680;\n\t"
        "@P1 bra.uni WD_%=;\n\t"
        "bra.uni WL_%=;\n\t"
        "WD_%=:\n\t"
        "}"
        :: "r"(mbar), "r"(parity) : "memory");
}

__global__ void __cluster_dims__(CL, 1, 1) __launch_bounds__(TPB, 1)
scan_kernel(const float* __restrict__ G, const float* __restrict__ Rw,
            float* __restrict__ out)
{
    __shared__ __align__(16) float hs[2 * BUFSTR];    // double-buffered h (padded)
    __shared__ __align__(16) float stage[2][EPB];     // outgoing h chunks (double-buffered)
    __shared__ float pres2[2][192];                   // per-thread partials (double-buffered)
    __shared__ __align__(8) unsigned long long fm[4]; // [buf*2 + sel] tx barriers

    const int tid  = threadIdx.x;
    const int grp  = blockIdx.x >> 3;      // (b,h) group 0..15
    const int rank = blockIdx.x & (CL - 1);
    const int b = grp >> 2;
    const int h = grp & 3;

    const int o    = tid % 96;             // output 0..95  (g*EPB + e)
    const int half = tid / 96;             // d-range half: [96*half, 96*half+96)
    const int dg   = o / EPB;
    const int de   = o % EPB;
    const int col  = rank * EPB + de;

    // ---- R slice packed into f32x2 regs: 96 floats = 48 pairs
    uint64_t Rp[48];
    {
        const float* Rb = Rw + ((size_t)(dg * NH_ + h) * DH_ + half * 96) * DH_ + col;
#pragma unroll
        for (int i = 0; i < 24; i++) {
            float r0 = Rb[(size_t)(4 * i + 0) * DH_];
            float r1 = Rb[(size_t)(4 * i + 1) * DH_];
            float r2 = Rb[(size_t)(4 * i + 2) * DH_];
            float r3 = Rb[(size_t)(4 * i + 3) * DH_];
            asm("mov.b64 %0, {%1, %2};" : "=l"(Rp[2 * i])     : "f"(r0), "f"(r1));
            asm("mov.b64 %0, {%1, %2};" : "=l"(Rp[2 * i + 1]) : "f"(r2), "f"(r3));
        }
    }

    for (int i = tid; i < 2 * BUFSTR; i += TPB) hs[i] = 0.f;
    const uint32_t fm_local = (uint32_t)__cvta_generic_to_shared(&fm[0]);
    if (tid == 0) {
#pragma unroll
        for (int q = 0; q < 4; q++) {
            asm volatile("mbarrier.init.shared.b64 [%0], %1;" :: "r"(fm_local + q * 8), "r"(1) : "memory");
            asm volatile("mbarrier.arrive.expect_tx.shared.b64 _, [%0], %1;"
                         :: "r"(fm_local + q * 8), "r"(TXH) : "memory");
        }
    }
    __syncthreads();
    asm volatile("barrier.cluster.arrive.aligned;" ::: "memory");
    asm volatile("barrier.cluster.wait.aligned;"   ::: "memory");

    // sender thread (SEND0+r) ships this CTA's 96B chunk to rank r.
    // dst slot (buffer 0) = hs + (rank/2)*QSTR + (rank&1)*EPB in CTA r;
    // dest barrier sel by SOURCE rank: ranks 0-3 -> fmA(sel 0), 4-7 -> fmB(sel 1)
    uint32_t hrem = 0, frem = 0;
    const int mysel = (rank >= 4) ? 1 : 0;
    if (tid >= SEND0) {
        int dr = tid - SEND0;              // destination rank
        uint32_t la = (uint32_t)__cvta_generic_to_shared(
            &hs[(rank >> 1) * QSTR + (rank & 1) * EPB]);
        asm volatile("mapa.shared::cluster.u32 %0, %1, %2;" : "=r"(hrem) : "r"(la), "r"(dr));
        asm volatile("mapa.shared::cluster.u32 %0, %1, %2;" : "=r"(frem) : "r"(fm_local), "r"(dr));
    }
    const uint32_t stage_base = (uint32_t)__cvta_generic_to_shared(&stage[0][0]);

    const float* Gp = G + (size_t)(b * 16 + h * 4 + dg) * DH_ + col;
    const int GSTRIDE = B_ * 16 * DH_;     // 12288
    float gin = (half == 0) ? Gp[0] : 0.f;

    float c = 0.f, n = 0.f, mst = 0.f;
    const int ge = tid - GATE0;            // gating element, valid for 0<=ge<EPB
    float* outp = out + (size_t)b * S_ * D_ + h * DH_ + rank * EPB + ge;
    int ph0 = 0, ph1 = 0;
    const uint32_t mybar_off = (uint32_t)(half * 8);   // this thread's half barrier

#pragma unroll 1
    for (int t = 0; t < S_; ++t) {
        const int j = t & 1;
        if (t > 0) {
            uint32_t bar = fm_local + (uint32_t)(j * 16) + mybar_off;
            if (j) { mbar_wait_cta(bar, (uint32_t)ph1); ph1 ^= 1; }
            else   { mbar_wait_cta(bar, (uint32_t)ph0); ph0 ^= 1; }
            // re-arm this buffer's half-barriers for step t+2's data
            if (tid == 0)
                asm volatile("mbarrier.arrive.expect_tx.shared.b64 _, [%0], %1;"
                             :: "r"(fm_local + j * 16), "r"(TXH) : "memory");
            if (tid == 191)
                asm volatile("mbarrier.arrive.expect_tx.shared.b64 _, [%0], %1;"
                             :: "r"(fm_local + j * 16 + 8), "r"(TXH) : "memory");
        }

        // dot over d-range [96*half, 96*half+96): quarters 2*half and 2*half+1
        const ulonglong2* hvA = (const ulonglong2*)(hs + j * BUFSTR + (2 * half) * QSTR);
        const ulonglong2* hvB = (const ulonglong2*)(hs + j * BUFSTR + (2 * half + 1) * QSTR);
        uint64_t acc01 = 0ull, acc23 = 0ull;     // packed {0.f, 0.f}
#pragma unroll
        for (int i = 0; i < 12; i++) {
            ulonglong2 hp = hvA[i];
            asm("fma.rn.f32x2 %0, %1, %2, %0;" : "+l"(acc01) : "l"(Rp[2 * i]),     "l"(hp.x));
            asm("fma.rn.f32x2 %0, %1, %2, %0;" : "+l"(acc23) : "l"(Rp[2 * i + 1]), "l"(hp.y));
        }
#pragma unroll
        for (int i = 0; i < 12; i++) {
            ulonglong2 hp = hvB[i];
            asm("fma.rn.f32x2 %0, %1, %2, %0;" : "+l"(acc01) : "l"(Rp[24 + 2 * i]),     "l"(hp.x));
            asm("fma.rn.f32x2 %0, %1, %2, %0;" : "+l"(acc23) : "l"(Rp[24 + 2 * i + 1]), "l"(hp.y));
        }
        float a0, a1, a2, a3;
        asm("mov.b64 {%0, %1}, %2;" : "=f"(a0), "=f"(a1) : "l"(acc01));
        asm("mov.b64 {%0, %1}, %2;" : "=f"(a2), "=f"(a3) : "l"(acc23));
        float sum = (a0 + a1) + (a2 + a3);
        if (half == 0) {
            pres2[j][tid] = sum + gin;
            if (t + 1 < S_) gin = Gp[(size_t)(t + 1) * GSTRIDE];   // prefetch
        } else {
            pres2[j][tid] = sum;
        }

        if (tid < GATE0) {
            // dot warps: arrive and drop straight into next step's mbar sleep.
            asm volatile("bar.arrive 1, 192;" ::: "memory");
        } else {
            asm volatile("bar.sync 1, 192;" ::: "memory");    // S1 (warp 5)
            float hnew = 0.f;
            if (tid < GATE0 + EPB) {
                float it = pres2[j][ge]      + pres2[j][96 + ge];
                float ft = pres2[j][24 + ge] + pres2[j][120 + ge];
                float zt = pres2[j][48 + ge] + pres2[j][144 + ge];
                float ot = pres2[j][72 + ge] + pres2[j][168 + ge];
                float fmv = ft + mst;
                float d   = it - fmv;                     // mn = max(fmv, it)
                float e   = __expf(-fabsf(d));            // single MUFU for ia/fa
                float ia  = (d >= 0.f) ? 1.f : e;         // exp(it - mn)
                float fa  = (d >= 0.f) ? e : 1.f;         // exp(fmv - mn)
                mst = fmaxf(fmv, it);
                float e2 = __expf(2.f * zt);
                float tz = 1.f - __fdividef(2.f, e2 + 1.f);   // tanh, NaN-safe
                c = fa * c + ia * tz;
                n = fa * n + ia;
                float es = __expf(-ot);
                hnew = __fdividef(c, fmaf(n, es, n));     // sigmoid(ot)*c/n, fused
                stage[j][ge] = hnew;
            }
            __syncwarp();                             // warp 5: stage visible to senders
            if (t + 1 < S_ && tid >= SEND0) {
                asm volatile("fence.proxy.async.shared::cta;" ::: "memory");
                uint32_t dst = hrem + (uint32_t)((j ^ 1) * (BUFSTR * 4));
                uint32_t mb  = frem + (uint32_t)((j ^ 1) * 16 + mysel * 8);
                uint32_t src = stage_base + (uint32_t)(j * (EPB * 4));
                asm volatile(
                    "cp.async.bulk.shared::cluster.shared::cta.mbarrier::complete_tx::bytes "
                    "[%0], [%1], %2, [%3];"
                    :: "r"(dst), "r"(src), "r"((uint32_t)(EPB * 4)), "r"(mb) : "memory");
            }
            if (tid < GATE0 + EPB)
                outp[(size_t)t * D_] = hnew;          // global store after sends
        }
    }

    asm volatile("barrier.cluster.arrive.aligned;" ::: "memory");
    asm volatile("barrier.cluster.wait.aligned;"   ::: "memory");
}

// ---------------------------------------------------------------------------
// 4) in-place multi-head LayerNorm over DH per (b,s,h); warp per row
// ---------------------------------------------------------------------------
__global__ __launch_bounds__(256) void gnorm_kernel(
    float* __restrict__ out, const float* __restrict__ gs)
{
    int warp = (blockIdx.x * 256 + threadIdx.x) >> 5;  // row id, 32768 rows
    int lane = threadIdx.x & 31;
    float* base = out + (size_t)warp * DH_;
    int h = warp & (NH_ - 1);

    float v[6], s = 0.f, sq = 0.f;
#pragma unroll
    for (int j = 0; j < 6; j++) {
        v[j] = base[lane + 32 * j];
        s += v[j];
        sq += v[j] * v[j];
    }
#pragma unroll
    for (int o = 16; o > 0; o >>= 1) {
        s += __shfl_xor_sync(0xFFFFFFFFu, s, o);
        sq += __shfl_xor_sync(0xFFFFFFFFu, sq, o);
    }
    float mean = s * (1.f / DH_);
    float var = sq * (1.f / DH_) - mean * mean;
    float inv = rsqrtf(var + 1e-5f);
#pragma unroll
    for (int j = 0; j < 6; j++)
        base[lane + 32 * j] = (v[j] - mean) * inv * gs[h * DH_ + lane + 32 * j];
}

// ---------------------------------------------------------------------------
// launcher
// ---------------------------------------------------------------------------
extern "C" void kernel_launch(void* const* d_in, const int* in_sizes, int n_in,
                              void* d_out, int out_size)
{
    const float* x   = (const float*)d_in[0];
    const float* ck  = (const float*)d_in[1];
    const float* cb  = (const float*)d_in[2];
    const float* Wi  = (const float*)d_in[3];
    const float* Wf  = (const float*)d_in[4];
    const float* Wz  = (const float*)d_in[5];
    const float* Wo  = (const float*)d_in[6];
    const float* Rw  = (const float*)d_in[7];
    const float* cbias = (const float*)d_in[8];
    const float* gsc = (const float*)d_in[9];
    float* out = (float*)d_out;

    float* xconv; float* G;
    cudaGetSymbolAddress((void**)&xconv, d_xconv);
    cudaGetSymbolAddress((void**)&G, d_G);

    // 1) conv + swish
    conv_swish_kernel<<<(B_ * S_ * D_) / 256, 256>>>(x, ck, cb, xconv);

    // 2) gate GEMMs (R10 config: 128x64 tiles, 256 threads)
    dim3 ggrid((B_ * S_) / 128, DH_ / 64, NH_ * 4);
    gate_gemm_kernel<<<ggrid, 256>>>(x, xconv, Wi, Wf, Wz, Wo, cbias, G);

    // 3) scan (clustered: split-half barriers, shfl-free reduction)
    scan_kernel<<<B_ * NH_ * CL, TPB>>>(G, Rw, out);

    // 4) per-head layernorm in-place
    gnorm_kernel<<<(B_ * S_ * NH_) / 8, 256>>>(out, gsc);
}